// round 1
// baseline (speedup 1.0000x reference)
#include <cuda_runtime.h>
#include <math.h>

// Problem dims
#define Bb   256   // batch
#define Ss   512   // encoder sequence
#define Hh   256   // hidden
#define OUTD 3     // output size
#define NST  64    // steps to predict
#define INW  259   // LSTM input width (OUT + H)
#define G4   (4*Hh)

// Output layout (concatenated flattened outputs in reference return order)
#define OFF_PRED 0
#define OFF_HID  (Bb*NST*OUTD)          // 49152
#define OFF_ATT  (OFF_HID + Bb*Hh)      // 114688

// Persistent device state (no allocations allowed)
__device__ float g_h[Bb*Hh];
__device__ float g_c[Bb*Hh];
__device__ float g_x[Bb*OUTD];
__device__ float g_v[Bb*Hh];
__device__ float g_ctx[Bb*Hh];
__device__ float g_gates[Bb*G4];
__device__ float g_Wcat[G4*512];   // [j][k]: k<256 -> W_ih[j,3+k], else W_hh[j,k-256]
__device__ float g_Wx[G4*OUTD];    // W_ih[j,0..2]
__device__ float g_bias[G4];       // b_ih + b_hh

__device__ __forceinline__ float warp_sum(float v){
  #pragma unroll
  for (int o = 16; o; o >>= 1) v += __shfl_xor_sync(0xffffffffu, v, o);
  return v;
}
__device__ __forceinline__ float sigmoidf(float x){ return 1.f/(1.f+expf(-x)); }

// ---------------------------------------------------------------- init/pack
__global__ void k_init(const float* __restrict__ eh, const float* __restrict__ ec){
  int i = blockIdx.x*blockDim.x + threadIdx.x;
  if (i < Bb*Hh){ g_h[i] = eh[i]; g_c[i] = ec[i]; }
  if (i < Bb*OUTD) g_x[i] = 0.f;
}

__global__ void k_pack(const float* __restrict__ Wih, const float* __restrict__ Whh,
                       const float* __restrict__ bih, const float* __restrict__ bhh){
  int j = blockIdx.x;       // 0..1023
  int k = threadIdx.x;      // 0..511
  g_Wcat[j*512 + k] = (k < Hh) ? Wih[j*INW + OUTD + k] : Whh[j*Hh + (k - Hh)];
  if (k < OUTD) g_Wx[j*OUTD + k] = Wih[j*INW + k];
  if (k == 0)   g_bias[j] = bih[j] + bhh[j];
}

// ---------------------------------------------------------------- wq -> v
// wq[b,g] = sum_k h[b,k]*Wa[g,k] + ba[g]
// v[b,h]  = sum_g wq[b,g]*Ua[g,h]   (score bias term is softmax-invariant: dropped)
__device__ __forceinline__ void wqv_body(int b, int tid,
                                         const float* __restrict__ Wa,
                                         const float* __restrict__ ba,
                                         const float* __restrict__ Ua,
                                         const float* h_s, float* wq_s){
  int wid = tid >> 5, lane = tid & 31;
  for (int g = wid; g < Hh; g += 8){
    const float4* wrow = (const float4*)(Wa + g*Hh);
    float acc = 0.f;
    #pragma unroll
    for (int cch = 0; cch < 2; cch++){
      float4 w4 = wrow[cch*32 + lane];
      int k = cch*128 + lane*4;
      acc = fmaf(w4.x, h_s[k],   acc);
      acc = fmaf(w4.y, h_s[k+1], acc);
      acc = fmaf(w4.z, h_s[k+2], acc);
      acc = fmaf(w4.w, h_s[k+3], acc);
    }
    acc = warp_sum(acc);
    if (!lane) wq_s[g] = acc + ba[g];
  }
  __syncthreads();
  float acc = 0.f;
  #pragma unroll 4
  for (int g = 0; g < Hh; g++) acc = fmaf(wq_s[g], Ua[g*Hh + tid], acc);
  g_v[b*Hh + tid] = acc;
}

__global__ void k_wqv(const float* __restrict__ Wa, const float* __restrict__ ba,
                      const float* __restrict__ Ua){
  __shared__ float h_s[Hh];
  __shared__ float wq_s[Hh];
  int b = blockIdx.x, tid = threadIdx.x;
  h_s[tid] = g_h[b*Hh + tid];
  __syncthreads();
  wqv_body(b, tid, Wa, ba, Ua, h_s, wq_s);
}

// ---------------------------------------------------------------- attention
// One block per batch b (256 threads): scores (warp-per-row dot), block softmax,
// weighted-sum context (coalesced column access). Writes attentions + g_ctx.
__global__ void k_attn(const float* __restrict__ enc, float* __restrict__ out, int t){
  __shared__ float v_s[Hh];
  __shared__ float w_s[Ss];
  __shared__ float r_s[8];
  int b = blockIdx.x, tid = threadIdx.x, wid = tid >> 5, lane = tid & 31;
  v_s[tid] = g_v[b*Hh + tid];
  __syncthreads();
  const float* encb = enc + (size_t)b*Ss*Hh;

  // scores
  for (int s = wid; s < Ss; s += 8){
    const float4* row = (const float4*)(encb + (size_t)s*Hh);
    float acc = 0.f;
    #pragma unroll
    for (int cch = 0; cch < 2; cch++){
      float4 e4 = row[cch*32 + lane];
      int k = cch*128 + lane*4;
      acc = fmaf(e4.x, v_s[k],   acc);
      acc = fmaf(e4.y, v_s[k+1], acc);
      acc = fmaf(e4.z, v_s[k+2], acc);
      acc = fmaf(e4.w, v_s[k+3], acc);
    }
    acc = warp_sum(acc);
    if (!lane) w_s[s] = acc;
  }
  __syncthreads();

  // softmax over 512 (2 elements/thread)
  float a0 = w_s[tid], a1 = w_s[tid + 256];
  float m = fmaxf(a0, a1);
  #pragma unroll
  for (int o = 16; o; o >>= 1) m = fmaxf(m, __shfl_xor_sync(0xffffffffu, m, o));
  if (!lane) r_s[wid] = m;
  __syncthreads();
  m = r_s[0];
  #pragma unroll
  for (int i = 1; i < 8; i++) m = fmaxf(m, r_s[i]);
  float e0 = expf(a0 - m), e1 = expf(a1 - m);
  float psum = warp_sum(e0 + e1);
  __syncthreads();
  if (!lane) r_s[wid] = psum;
  __syncthreads();
  float tot = 0.f;
  #pragma unroll
  for (int i = 0; i < 8; i++) tot += r_s[i];
  float inv = 1.f / tot;
  e0 *= inv; e1 *= inv;
  w_s[tid] = e0; w_s[tid + 256] = e1;
  float* att = out + OFF_ATT + ((size_t)b*NST + t)*Ss;
  att[tid] = e0; att[tid + 256] = e1;
  __syncthreads();

  // context: ctx[b,h] = sum_s w[s]*enc[b,s,h]  (coalesced over h = tid)
  float acc = 0.f;
  const float* col = encb + tid;
  #pragma unroll 8
  for (int s = 0; s < Ss; s++) acc = fmaf(w_s[s], col[(size_t)s*Hh], acc);
  g_ctx[b*Hh + tid] = acc;
}

// ---------------------------------------------------------------- gates GEMM
// gates[b,j] = ctx[b,:]@Wcat[j,0:256] + h[b,:]@Wcat[j,256:512]
//            + bias[j] + x[b,:]@Wx[j,:]
#define BM 64
#define BN 32
#define BK 32
__global__ void k_gates(){
  __shared__ float As[BK][BM + 4];   // [k][m]
  __shared__ float Bs[BK][BN + 4];   // [k][n]
  int tid = threadIdx.x;             // 128 threads
  int m0 = blockIdx.y * BM, n0 = blockIdx.x * BN;
  int tx = tid & 7, ty = tid >> 3;   // tx: 0..7 (n), ty: 0..15 (m)
  float acc[4][4] = {};
  int c4 = (tid & 7) << 2, r = tid >> 3;

  for (int kt = 0; kt < 512; kt += BK){
    const float* Abase = (kt < Hh) ? (g_ctx + kt) : (g_h + kt - Hh);
    #pragma unroll
    for (int i = 0; i < 4; i++){
      int rr = r + 16*i;
      float4 a4 = *(const float4*)(Abase + (m0 + rr)*Hh + c4);
      As[c4+0][rr] = a4.x; As[c4+1][rr] = a4.y;
      As[c4+2][rr] = a4.z; As[c4+3][rr] = a4.w;
    }
    #pragma unroll
    for (int i = 0; i < 2; i++){
      int rr = r + 16*i;
      float4 b4 = *(const float4*)(g_Wcat + (size_t)(n0 + rr)*512 + kt + c4);
      Bs[c4+0][rr] = b4.x; Bs[c4+1][rr] = b4.y;
      Bs[c4+2][rr] = b4.z; Bs[c4+3][rr] = b4.w;
    }
    __syncthreads();
    #pragma unroll
    for (int kk = 0; kk < BK; kk++){
      float4 a4 = *(const float4*)(&As[kk][ty*4]);
      float4 b4 = *(const float4*)(&Bs[kk][tx*4]);
      float av[4] = {a4.x, a4.y, a4.z, a4.w};
      float bv[4] = {b4.x, b4.y, b4.z, b4.w};
      #pragma unroll
      for (int i = 0; i < 4; i++)
        #pragma unroll
        for (int j = 0; j < 4; j++)
          acc[i][j] = fmaf(av[i], bv[j], acc[i][j]);
    }
    __syncthreads();
  }

  #pragma unroll
  for (int i = 0; i < 4; i++){
    int bidx = m0 + ty*4 + i;
    float x0 = g_x[bidx*OUTD+0], x1 = g_x[bidx*OUTD+1], x2 = g_x[bidx*OUTD+2];
    #pragma unroll
    for (int j = 0; j < 4; j++){
      int n = n0 + tx*4 + j;
      float val = acc[i][j] + g_bias[n]
                + x0*g_Wx[n*OUTD+0] + x1*g_Wx[n*OUTD+1] + x2*g_Wx[n*OUTD+2];
      g_gates[(size_t)bidx*G4 + n] = val;
    }
  }
}

// ---------------------------------------------------------------- LSTM + pred + next wq/v
__global__ void k_lstm(const float* __restrict__ Wo, const float* __restrict__ bo,
                       const float* __restrict__ Wa, const float* __restrict__ ba,
                       const float* __restrict__ Ua,
                       float* __restrict__ out, int t){
  __shared__ float h_s[Hh];
  __shared__ float wq_s[Hh];
  int b = blockIdx.x, tid = threadIdx.x, wid = tid >> 5, lane = tid & 31;
  const float* gb = g_gates + (size_t)b*G4;
  float gi = gb[tid], gf = gb[Hh + tid], gg = gb[2*Hh + tid], go = gb[3*Hh + tid];
  float c  = g_c[b*Hh + tid];
  float cn = sigmoidf(gf)*c + sigmoidf(gi)*tanhf(gg);
  float hn = sigmoidf(go)*tanhf(cn);
  g_c[b*Hh + tid] = cn;
  g_h[b*Hh + tid] = hn;
  h_s[tid] = hn;
  if (t == NST-1) out[OFF_HID + b*Hh + tid] = hn;
  __syncthreads();

  // prediction: 3 dots of length 256 (warps 0..2)
  if (wid < 3){
    float a = 0.f;
    #pragma unroll
    for (int k = lane; k < Hh; k += 32) a = fmaf(h_s[k], Wo[wid*Hh + k], a);
    a = warp_sum(a);
    if (!lane){
      float p = a + bo[wid];
      out[OFF_PRED + ((size_t)b*NST + t)*OUTD + wid] = p;
      g_x[b*OUTD + wid] = p;   // autoregressive feedback
    }
  }

  // fused: compute next step's wq and v from h_new already in smem
  wqv_body(b, tid, Wa, ba, Ua, h_s, wq_s);
}

// ---------------------------------------------------------------- launch
extern "C" void kernel_launch(void* const* d_in, const int* in_sizes, int n_in,
                              void* d_out, int out_size){
  const float* enc  = (const float*)d_in[0];
  const float* ehid = (const float*)d_in[1];
  const float* ecell= (const float*)d_in[2];
  const float* Wa   = (const float*)d_in[3];
  const float* ba   = (const float*)d_in[4];
  const float* Ua   = (const float*)d_in[5];
  /* bua = d_in[6] is softmax-invariant (constant per batch): unused */
  const float* Wih  = (const float*)d_in[7];
  const float* Whh  = (const float*)d_in[8];
  const float* bih  = (const float*)d_in[9];
  const float* bhh  = (const float*)d_in[10];
  const float* Wo   = (const float*)d_in[11];
  const float* bo   = (const float*)d_in[12];
  float* out = (float*)d_out;

  k_init<<<256, 256>>>(ehid, ecell);
  k_pack<<<G4, 512>>>(Wih, Whh, bih, bhh);
  k_wqv<<<Bb, 256>>>(Wa, ba, Ua);
  for (int t = 0; t < NST; t++){
    k_attn<<<Bb, 256>>>(enc, out, t);
    k_gates<<<dim3(1024/BN, Bb/BM), 128>>>();
    k_lstm<<<Bb, 256>>>(Wo, bo, Wa, ba, Ua, out, t);
  }
}

// round 2
// speedup vs baseline: 1.8365x; 1.8365x over previous
#include <cuda_runtime.h>
#include <math.h>

// Problem dims
#define Bb   256   // batch
#define Ss   512   // encoder sequence
#define Hh   256   // hidden
#define OUTD 3     // output size
#define NST  64    // steps
#define INW  259   // LSTM input width (OUT + H)
#define G4   (4*Hh)
#define NSLICE 4
#define SLROWS (Ss/NSLICE)   // 128

// Output layout
#define OFF_PRED 0
#define OFF_HID  (Bb*NST*OUTD)          // 49152
#define OFF_ATT  (OFF_HID + Bb*Hh)      // 114688

// Persistent device state
__device__ float g_h[Bb*Hh];
__device__ float g_c[Bb*Hh];
__device__ float g_x[Bb*OUTD];
__device__ float g_v[Bb*Hh];
__device__ float g_ctx[Bb*Hh];
__device__ float g_gates[Bb*G4];
__device__ float g_Wcat[G4*512];   // [j][k]: k<256 -> W_ih[j,3+k], else W_hh[j,k-256]
__device__ float g_Wx[G4*OUTD];
__device__ float g_bias[G4];
__device__ float g_M[Hh*Hh];       // M[k*256+j] = sum_g Wa[g,k]*Ua[g,j]
__device__ float g_vb[Hh];         // vb[j] = sum_g ba[g]*Ua[g,j]
// attention partials (per batch, per slice)
__device__ float g_pm[Bb*NSLICE];
__device__ float g_pl[Bb*NSLICE];
__device__ float g_pctx[Bb*NSLICE*Hh];

__device__ __forceinline__ float warp_sum(float v){
  #pragma unroll
  for (int o = 16; o; o >>= 1) v += __shfl_xor_sync(0xffffffffu, v, o);
  return v;
}
__device__ __forceinline__ float sigmoidf_(float x){ return 1.f/(1.f+expf(-x)); }

// ---------------------------------------------------------------- init/pack/prep
__global__ void k_init(const float* __restrict__ eh, const float* __restrict__ ec){
  int i = blockIdx.x*blockDim.x + threadIdx.x;
  if (i < Bb*Hh){ g_h[i] = eh[i]; g_c[i] = ec[i]; }
  if (i < Bb*OUTD) g_x[i] = 0.f;
}

__global__ void k_pack(const float* __restrict__ Wih, const float* __restrict__ Whh,
                       const float* __restrict__ bih, const float* __restrict__ bhh){
  int j = blockIdx.x, k = threadIdx.x;
  g_Wcat[j*512 + k] = (k < Hh) ? Wih[j*INW + OUTD + k] : Whh[j*Hh + (k - Hh)];
  if (k < OUTD) g_Wx[j*OUTD + k] = Wih[j*INW + k];
  if (k == 0)   g_bias[j] = bih[j] + bhh[j];
}

// M = Wa^T @ Ua ; vb = ba @ Ua  (grid 257: blocks 0..255 -> M rows, 256 -> vb)
__global__ void k_prep(const float* __restrict__ Wa, const float* __restrict__ ba,
                       const float* __restrict__ Ua){
  int kk = blockIdx.x, j = threadIdx.x;
  float a = 0.f;
  if (kk < Hh){
    #pragma unroll 4
    for (int g = 0; g < Hh; g++) a = fmaf(Wa[g*Hh + kk], Ua[g*Hh + j], a);
    g_M[kk*Hh + j] = a;
  } else {
    #pragma unroll 4
    for (int g = 0; g < Hh; g++) a = fmaf(ba[g], Ua[g*Hh + j], a);
    g_vb[j] = a;
  }
}

// ---------------------------------------------------------------- v GEMM: v = h@M + vb
#define VBM 32
#define VBN 64
#define VBK 16
__global__ void k_v(){
  __shared__ float As[VBK][VBM + 4];
  __shared__ float Bs[VBK][VBN + 4];
  int tid = threadIdx.x;                 // 256
  int j0 = blockIdx.x * VBN, b0 = blockIdx.y * VBM;
  int tx = tid & 15, ty = tid >> 4;      // tx: j(x4), ty: b(x2)
  float acc[2][4] = {};
  for (int kt = 0; kt < Hh; kt += VBK){
    if (tid < 128){
      int row = tid >> 2, c4 = (tid & 3) << 2;
      float4 a4 = *(const float4*)(g_h + (b0 + row)*Hh + kt + c4);
      As[c4+0][row] = a4.x; As[c4+1][row] = a4.y;
      As[c4+2][row] = a4.z; As[c4+3][row] = a4.w;
    }
    {
      int krow = tid >> 4, j4 = (tid & 15) << 2;
      float4 b4 = *(const float4*)(g_M + (size_t)(kt + krow)*Hh + j0 + j4);
      Bs[krow][j4+0] = b4.x; Bs[krow][j4+1] = b4.y;
      Bs[krow][j4+2] = b4.z; Bs[krow][j4+3] = b4.w;
    }
    __syncthreads();
    #pragma unroll
    for (int kk = 0; kk < VBK; kk++){
      float a0 = As[kk][ty*2], a1 = As[kk][ty*2+1];
      float4 b4 = *(const float4*)(&Bs[kk][tx*4]);
      acc[0][0] = fmaf(a0, b4.x, acc[0][0]); acc[0][1] = fmaf(a0, b4.y, acc[0][1]);
      acc[0][2] = fmaf(a0, b4.z, acc[0][2]); acc[0][3] = fmaf(a0, b4.w, acc[0][3]);
      acc[1][0] = fmaf(a1, b4.x, acc[1][0]); acc[1][1] = fmaf(a1, b4.y, acc[1][1]);
      acc[1][2] = fmaf(a1, b4.z, acc[1][2]); acc[1][3] = fmaf(a1, b4.w, acc[1][3]);
    }
    __syncthreads();
  }
  #pragma unroll
  for (int i = 0; i < 2; i++){
    int b = b0 + ty*2 + i;
    #pragma unroll
    for (int q = 0; q < 4; q++){
      int j = j0 + tx*4 + q;
      g_v[b*Hh + j] = acc[i][q] + g_vb[j];
    }
  }
}

// ---------------------------------------------------------------- attention (single-pass, sliced)
// grid (NSLICE, Bb), 256 threads. Online softmax over 4 tiles of 32 rows.
__global__ void k_attn(const float* __restrict__ enc, float* __restrict__ out, int t){
  __shared__ float tile[32][Hh];      // 32 KB
  __shared__ float v_s[Hh];
  __shared__ float ctx_s[Hh];
  __shared__ float tsc[32];
  __shared__ float wbuf[SLROWS];
  __shared__ float tmaxs[4];
  __shared__ float red0;
  int slice = blockIdx.x, b = blockIdx.y;
  int tid = threadIdx.x, wid = tid >> 5, lane = tid & 31;
  int s0 = slice * SLROWS;
  const float* encb = enc + (size_t)b*Ss*Hh;

  v_s[tid] = g_v[b*Hh + tid];
  ctx_s[tid] = 0.f;
  float m_run = -3.0e38f, l_run = 0.f;
  __syncthreads();

  for (int ti = 0; ti < 4; ti++){
    // load 32x256 tile
    const float4* src = (const float4*)(encb + (size_t)(s0 + ti*32)*Hh);
    float4* dst = (float4*)&tile[0][0];
    #pragma unroll
    for (int i = 0; i < 8; i++) dst[tid + 256*i] = src[tid + 256*i];
    __syncthreads();

    // scores: warp wid rows wid*4..+3
    #pragma unroll
    for (int r = 0; r < 4; r++){
      int s = wid*4 + r;
      float acc = 0.f;
      #pragma unroll
      for (int k = 0; k < 8; k++) acc = fmaf(tile[s][lane + 32*k], v_s[lane + 32*k], acc);
      acc = warp_sum(acc);
      if (!lane) tsc[s] = acc;
    }
    __syncthreads();

    // all threads: tile max (broadcast reads), new running max
    float mt = tsc[0];
    #pragma unroll
    for (int s = 1; s < 32; s++) mt = fmaxf(mt, tsc[s]);
    float m_new = fmaxf(m_run, mt);
    float scale = expf(m_run - m_new);

    // warp 0: exp weights + sum
    if (wid == 0){
      float e = expf(tsc[lane] - m_new);
      wbuf[ti*32 + lane] = e;
      float es = warp_sum(e);
      if (!lane){ red0 = es; tmaxs[ti] = m_new; }
    }
    __syncthreads();
    l_run = l_run * scale + red0;
    m_run = m_new;

    // ctx accumulate
    float c = ctx_s[tid] * scale;
    #pragma unroll
    for (int s = 0; s < 32; s++) c = fmaf(wbuf[ti*32 + s], tile[s][tid], c);
    ctx_s[tid] = c;
    __syncthreads();   // tile reuse guard
  }

  // emit partials; att entries normalized to local max (rescaled in k_comb)
  g_pctx[(b*NSLICE + slice)*Hh + tid] = ctx_s[tid];
  if (tid < SLROWS){
    float e = wbuf[tid] * expf(tmaxs[tid >> 5] - m_run);
    out[OFF_ATT + ((size_t)b*NST + t)*Ss + s0 + tid] = e;
  }
  if (tid == 0){
    g_pm[b*NSLICE + slice] = m_run;
    g_pl[b*NSLICE + slice] = l_run;
  }
}

// combine slices: final ctx + rescale attention weights in place
__global__ void k_comb(float* __restrict__ out, int t){
  int b = blockIdx.x, tid = threadIdx.x;
  float m0 = g_pm[b*NSLICE+0], m1 = g_pm[b*NSLICE+1];
  float m2 = g_pm[b*NSLICE+2], m3 = g_pm[b*NSLICE+3];
  float M = fmaxf(fmaxf(m0, m1), fmaxf(m2, m3));
  float f0 = expf(m0 - M), f1 = expf(m1 - M), f2 = expf(m2 - M), f3 = expf(m3 - M);
  float L = g_pl[b*NSLICE+0]*f0 + g_pl[b*NSLICE+1]*f1
          + g_pl[b*NSLICE+2]*f2 + g_pl[b*NSLICE+3]*f3;
  float inv = 1.f / L;
  float ctx = g_pctx[(b*NSLICE+0)*Hh + tid]*f0 + g_pctx[(b*NSLICE+1)*Hh + tid]*f1
            + g_pctx[(b*NSLICE+2)*Hh + tid]*f2 + g_pctx[(b*NSLICE+3)*Hh + tid]*f3;
  g_ctx[b*Hh + tid] = ctx * inv;
  float fs[4] = {f0*inv, f1*inv, f2*inv, f3*inv};
  float* att = out + OFF_ATT + ((size_t)b*NST + t)*Ss;
  att[tid]       *= fs[tid >> 7];
  att[tid + 256] *= fs[(tid + 256) >> 7];
}

// ---------------------------------------------------------------- gates GEMM
#define BM 64
#define BN 32
#define BK 32
__global__ void k_gates(){
  __shared__ float As[BK][BM + 4];
  __shared__ float Bs[BK][BN + 4];
  int tid = threadIdx.x;             // 256
  int m0 = blockIdx.y * BM, n0 = blockIdx.x * BN;
  int tx = tid & 7, ty = tid >> 3;   // tx: n(x4), ty: m(x2) 0..31
  float acc[2][4] = {};

  for (int kt = 0; kt < 512; kt += BK){
    const float* Abase = (kt < Hh) ? (g_ctx + kt) : (g_h + kt - Hh);
    #pragma unroll
    for (int i = 0; i < 2; i++){
      int idx = tid + 256*i;
      int rr = idx >> 3, c4 = (idx & 7) << 2;
      float4 a4 = *(const float4*)(Abase + (m0 + rr)*Hh + c4);
      As[c4+0][rr] = a4.x; As[c4+1][rr] = a4.y;
      As[c4+2][rr] = a4.z; As[c4+3][rr] = a4.w;
    }
    {
      int nrow = tid >> 3, c4 = (tid & 7) << 2;
      float4 b4 = *(const float4*)(g_Wcat + (size_t)(n0 + nrow)*512 + kt + c4);
      Bs[c4+0][nrow] = b4.x; Bs[c4+1][nrow] = b4.y;
      Bs[c4+2][nrow] = b4.z; Bs[c4+3][nrow] = b4.w;
    }
    __syncthreads();
    #pragma unroll
    for (int kk = 0; kk < BK; kk++){
      float a0 = As[kk][ty*2], a1 = As[kk][ty*2+1];
      float4 b4 = *(const float4*)(&Bs[kk][tx*4]);
      acc[0][0] = fmaf(a0, b4.x, acc[0][0]); acc[0][1] = fmaf(a0, b4.y, acc[0][1]);
      acc[0][2] = fmaf(a0, b4.z, acc[0][2]); acc[0][3] = fmaf(a0, b4.w, acc[0][3]);
      acc[1][0] = fmaf(a1, b4.x, acc[1][0]); acc[1][1] = fmaf(a1, b4.y, acc[1][1]);
      acc[1][2] = fmaf(a1, b4.z, acc[1][2]); acc[1][3] = fmaf(a1, b4.w, acc[1][3]);
    }
    __syncthreads();
  }

  #pragma unroll
  for (int i = 0; i < 2; i++){
    int bidx = m0 + ty*2 + i;
    float x0 = g_x[bidx*OUTD+0], x1 = g_x[bidx*OUTD+1], x2 = g_x[bidx*OUTD+2];
    #pragma unroll
    for (int q = 0; q < 4; q++){
      int n = n0 + tx*4 + q;
      g_gates[(size_t)bidx*G4 + n] = acc[i][q] + g_bias[n]
        + x0*g_Wx[n*OUTD+0] + x1*g_Wx[n*OUTD+1] + x2*g_Wx[n*OUTD+2];
    }
  }
}

// ---------------------------------------------------------------- LSTM elementwise + prediction
__global__ void k_lstm(const float* __restrict__ Wo, const float* __restrict__ bo,
                       float* __restrict__ out, int t){
  __shared__ float h_s[Hh];
  int b = blockIdx.x, tid = threadIdx.x, wid = tid >> 5, lane = tid & 31;
  const float* gb = g_gates + (size_t)b*G4;
  float gi = gb[tid], gf = gb[Hh + tid], gg = gb[2*Hh + tid], go = gb[3*Hh + tid];
  float c  = g_c[b*Hh + tid];
  float cn = sigmoidf_(gf)*c + sigmoidf_(gi)*tanhf(gg);
  float hn = sigmoidf_(go)*tanhf(cn);
  g_c[b*Hh + tid] = cn;
  g_h[b*Hh + tid] = hn;
  h_s[tid] = hn;
  if (t == NST-1) out[OFF_HID + b*Hh + tid] = hn;
  __syncthreads();
  if (wid < 3){
    float a = 0.f;
    #pragma unroll
    for (int k = lane; k < Hh; k += 32) a = fmaf(h_s[k], Wo[wid*Hh + k], a);
    a = warp_sum(a);
    if (!lane){
      float p = a + bo[wid];
      out[OFF_PRED + ((size_t)b*NST + t)*OUTD + wid] = p;
      g_x[b*OUTD + wid] = p;
    }
  }
}

// ---------------------------------------------------------------- launch
extern "C" void kernel_launch(void* const* d_in, const int* in_sizes, int n_in,
                              void* d_out, int out_size){
  const float* enc  = (const float*)d_in[0];
  const float* ehid = (const float*)d_in[1];
  const float* ecell= (const float*)d_in[2];
  const float* Wa   = (const float*)d_in[3];
  const float* ba   = (const float*)d_in[4];
  const float* Ua   = (const float*)d_in[5];
  /* d_in[6] (bua): softmax-invariant, unused */
  const float* Wih  = (const float*)d_in[7];
  const float* Whh  = (const float*)d_in[8];
  const float* bih  = (const float*)d_in[9];
  const float* bhh  = (const float*)d_in[10];
  const float* Wo   = (const float*)d_in[11];
  const float* bo   = (const float*)d_in[12];
  float* out = (float*)d_out;

  k_init<<<256, 256>>>(ehid, ecell);
  k_pack<<<G4, 512>>>(Wih, Whh, bih, bhh);
  k_prep<<<Hh + 1, 256>>>(Wa, ba, Ua);
  k_v<<<dim3(Hh/VBN, Bb/VBM), 256>>>();             // initial v from h0
  for (int t = 0; t < NST; t++){
    k_attn<<<dim3(NSLICE, Bb), 256>>>(enc, out, t);
    k_comb<<<Bb, 256>>>(out, t);
    k_gates<<<dim3(G4/BN, Bb/BM), 256>>>();
    k_lstm<<<Bb, 256>>>(Wo, bo, out, t);
    k_v<<<dim3(Hh/VBN, Bb/VBM), 256>>>();           // v for next step (dead at t=63, cheap)
  }
}